// round 1
// baseline (speedup 1.0000x reference)
#include <cuda_runtime.h>
#include <cuda_bf16.h>
#include <math.h>

// ---------------------------------------------------------------------------
// DecoderWithAttention: B=64, E=512, H=W=16, T=16, D=512, A=512, V=5000
// Pipeline of fp32 kernels, fully graph-capturable, scratch in __device__ bss.
// ---------------------------------------------------------------------------

#define B_ 64
#define E_ 512
#define T_ 16
#define D_ 512
#define P_ 256
#define A_ 512
#define V_ 5000

// ------------------------------ scratch ------------------------------------
__device__ float g_feats [T_ * B_ * E_];          // (T,B,E)
__device__ float g_fh    [B_ * P_ * E_];          // (B,P,E)
__device__ float g_Xp1f  [T_ * B_ * 4 * D_];
__device__ float g_Xp1r  [T_ * B_ * 4 * D_];
__device__ float g_Xp2f  [T_ * B_ * 4 * D_];
__device__ float g_Xp2r  [T_ * B_ * 4 * D_];
__device__ float g_x2    [T_ * B_ * 2 * D_];      // concat(h1s,h1r)
__device__ float g_hidden[T_ * B_ * 2 * D_];      // concat(h2s,h2r)
__device__ float g_state [3 * 128 * D_];          // hA | hB | c
__device__ float g_att1  [B_ * P_ * A_];
__device__ float g_att2  [T_ * B_ * A_];
__device__ float g_alpha [T_ * B_ * P_];
__device__ float g_awe   [T_ * B_ * E_];
__device__ float g_fcin  [T_ * B_ * (E_ + 2 * D_)];

// ------------------------------ utility ------------------------------------
__global__ void zero_kernel(float* __restrict__ p, int n) {
    int i = blockIdx.x * blockDim.x + threadIdx.x;
    if (i < n) p[i] = 0.f;
}

// fh[b][p][e] = enc[b][e][p]   (per-b 512x256 transpose)
__global__ void transpose_fh_kernel(const float* __restrict__ enc, float* __restrict__ fh) {
    __shared__ float tile[32][33];
    int b  = blockIdx.z;
    int e0 = blockIdx.x * 32;
    int p0 = blockIdx.y * 32;
    int x = threadIdx.x;
#pragma unroll
    for (int i = 0; i < 4; i++) {
        int y = threadIdx.y + i * 8;
        tile[y][x] = enc[((size_t)b * E_ + e0 + y) * P_ + p0 + x];
    }
    __syncthreads();
#pragma unroll
    for (int i = 0; i < 4; i++) {
        int y = threadIdx.y + i * 8;
        fh[((size_t)b * P_ + p0 + y) * E_ + e0 + x] = tile[x][y];
    }
}

// feats[t][b][e] = mean_h enc[b][e][h*16 + t]
__global__ void feats_kernel(const float* __restrict__ enc, float* __restrict__ feats) {
    int gi = blockIdx.x * blockDim.x + threadIdx.x;   // t fastest for coalesced reads
    if (gi >= T_ * B_ * E_) return;
    int t = gi & 15;
    int e = (gi >> 4) & (E_ - 1);
    int b = gi >> 13;
    const float* src = enc + ((size_t)b * E_ + e) * P_ + t;
    float s = 0.f;
#pragma unroll
    for (int h = 0; h < 16; h++) s += src[h * 16];
    feats[((size_t)t * B_ + b) * E_ + e] = s * (1.f / 16.f);
}

// ------------------------------ SGEMM (NT) ----------------------------------
// C[m][n] = sum_k A[m][k] * W[n][k] + b1[n] + b2[n]
// BM=BN=128, BK=8, 256 threads, 8x8 micro-tile. M % 128 == 0, K % 8 == 0.
__global__ __launch_bounds__(256) void sgemm_nt(
    const float* __restrict__ A, const float* __restrict__ W,
    const float* __restrict__ b1, const float* __restrict__ b2,
    float* __restrict__ C, int M, int N, int K)
{
    __shared__ float As[8][128];
    __shared__ float Bs[8][128];
    int tid  = threadIdx.x;
    int row0 = blockIdx.y * 128;
    int col0 = blockIdx.x * 128;
    int ty = tid >> 4;     // 0..15
    int tx = tid & 15;     // 0..15
    float acc[8][8];
#pragma unroll
    for (int i = 0; i < 8; i++)
#pragma unroll
        for (int j = 0; j < 8; j++) acc[i][j] = 0.f;

    int lm = tid >> 1;     // 0..127
    int lk = (tid & 1) * 4;

    for (int k0 = 0; k0 < K; k0 += 8) {
        float4 av = *(const float4*)(A + (size_t)(row0 + lm) * K + k0 + lk);
        As[lk + 0][lm] = av.x; As[lk + 1][lm] = av.y;
        As[lk + 2][lm] = av.z; As[lk + 3][lm] = av.w;

        int gn = col0 + lm;
        float4 bv = make_float4(0.f, 0.f, 0.f, 0.f);
        if (gn < N) bv = *(const float4*)(W + (size_t)gn * K + k0 + lk);
        Bs[lk + 0][lm] = bv.x; Bs[lk + 1][lm] = bv.y;
        Bs[lk + 2][lm] = bv.z; Bs[lk + 3][lm] = bv.w;
        __syncthreads();

#pragma unroll
        for (int kk = 0; kk < 8; kk++) {
            float4 a0 = *(const float4*)&As[kk][ty * 8];
            float4 a1 = *(const float4*)&As[kk][ty * 8 + 4];
            float4 b0 = *(const float4*)&Bs[kk][tx * 8];
            float4 b1v = *(const float4*)&Bs[kk][tx * 8 + 4];
            float a[8] = {a0.x, a0.y, a0.z, a0.w, a1.x, a1.y, a1.z, a1.w};
            float b[8] = {b0.x, b0.y, b0.z, b0.w, b1v.x, b1v.y, b1v.z, b1v.w};
#pragma unroll
            for (int i = 0; i < 8; i++)
#pragma unroll
                for (int j = 0; j < 8; j++) acc[i][j] += a[i] * b[j];
        }
        __syncthreads();
    }

#pragma unroll
    for (int i = 0; i < 8; i++) {
        int m = row0 + ty * 8 + i;
#pragma unroll
        for (int j = 0; j < 8; j++) {
            int n = col0 + tx * 8 + j;
            if (n < N) {
                float bias = 0.f;
                if (b1) bias += b1[n];
                if (b2) bias += b2[n];
                C[(size_t)m * N + n] = acc[i][j] + bias;
            }
        }
    }
}

// ------------------------------ fused LSTM step ------------------------------
// Rows 0..63 = fwd batch at time t (weights Whf, Xpf[t]);
// rows 64..127 = rev batch (weights Whr, Xpr[15-t]).
// Block owns d-slice [d0, d0+8). Computes gates = hIn @ Whh.T + Xp, then
// LSTM pointwise; writes h into hOut (state) and into the concat output
// buffer (fwd -> [t][b][0:512], rev -> [15-t][b][512:1024]).
__global__ __launch_bounds__(256) void lstm_step_kernel(
    const float* __restrict__ Xpf, const float* __restrict__ Xpr,
    const float* __restrict__ Whf, const float* __restrict__ Whr,
    const float* __restrict__ hIn, float* __restrict__ hOut,
    float* __restrict__ cbuf, float* __restrict__ outbuf, int t)
{
    __shared__ float hs[16][128];
    __shared__ float wfs[16][32];
    __shared__ float wrs[16][32];
    __shared__ float sg[128][33];

    int tid = threadIdx.x;
    int d0  = blockIdx.x * 8;
    int ty  = tid >> 3;   // 0..31 (rows ty*4..+3)
    int tx  = tid & 7;    // 0..7  (cols tx*4..+3)
    float acc[4][4];
#pragma unroll
    for (int i = 0; i < 4; i++)
#pragma unroll
        for (int j = 0; j < 4; j++) acc[i][j] = 0.f;

    for (int k0 = 0; k0 < D_; k0 += 16) {
        // h tile: 128x16 (512 float4, 2 per thread)
#pragma unroll
        for (int i = 0; i < 2; i++) {
            int idx = tid + i * 256;
            int m = idx >> 2, kq = idx & 3;
            float4 v = *(const float4*)(hIn + (size_t)m * D_ + k0 + kq * 4);
            hs[kq * 4 + 0][m] = v.x; hs[kq * 4 + 1][m] = v.y;
            hs[kq * 4 + 2][m] = v.z; hs[kq * 4 + 3][m] = v.w;
        }
        // W tiles: 32x16 each; threads 0-127 -> fwd, 128-255 -> rev
        {
            int half = tid >> 7;
            int idx  = tid & 127;
            int c = idx >> 2, kq = idx & 3;
            int wrow = (c >> 3) * D_ + d0 + (c & 7);
            const float* Wsrc = half ? Whr : Whf;
            float4 v = *(const float4*)(Wsrc + (size_t)wrow * D_ + k0 + kq * 4);
            float (*ws)[32] = half ? wrs : wfs;
            ws[kq * 4 + 0][c] = v.x; ws[kq * 4 + 1][c] = v.y;
            ws[kq * 4 + 2][c] = v.z; ws[kq * 4 + 3][c] = v.w;
        }
        __syncthreads();
        const float (*wsel)[32] = (ty < 16) ? wfs : wrs;
#pragma unroll
        for (int kk = 0; kk < 16; kk++) {
            float4 av = *(const float4*)&hs[kk][ty * 4];
            float4 bv = *(const float4*)&wsel[kk][tx * 4];
            float a[4] = {av.x, av.y, av.z, av.w};
            float b[4] = {bv.x, bv.y, bv.z, bv.w};
#pragma unroll
            for (int i = 0; i < 4; i++)
#pragma unroll
                for (int j = 0; j < 4; j++) acc[i][j] += a[i] * b[j];
        }
        __syncthreads();
    }

    // add x-projection and stage gates in smem
#pragma unroll
    for (int i = 0; i < 4; i++) {
        int r = ty * 4 + i;
        const float* xp = (r < 64)
            ? (Xpf + ((size_t)t * B_ + r) * (4 * D_))
            : (Xpr + ((size_t)(15 - t) * B_ + (r - 64)) * (4 * D_));
#pragma unroll
        for (int j = 0; j < 4; j++) {
            int c = tx * 4 + j;
            int gcol = (c >> 3) * D_ + d0 + (c & 7);
            sg[r][c] = acc[i][j] + xp[gcol];
        }
    }
    __syncthreads();

    // LSTM pointwise: 128 rows x 8 d = 1024 items
#pragma unroll
    for (int i = 0; i < 4; i++) {
        int item = tid + i * 256;
        int r = item >> 3, dj = item & 7;
        int d = d0 + dj;
        float iv = sg[r][dj];
        float fv = sg[r][8 + dj];
        float gv = sg[r][16 + dj];
        float ov = sg[r][24 + dj];
        float co = cbuf[(size_t)r * D_ + d];
        float si = 1.f / (1.f + expf(-iv));
        float sf = 1.f / (1.f + expf(-fv));
        float so = 1.f / (1.f + expf(-ov));
        float cn = sf * co + si * tanhf(gv);
        float hv = so * tanhf(cn);
        cbuf[(size_t)r * D_ + d] = cn;
        hOut[(size_t)r * D_ + d] = hv;
        if (r < 64)
            outbuf[((size_t)t * B_ + r) * (2 * D_) + d] = hv;
        else
            outbuf[((size_t)(15 - t) * B_ + (r - 64)) * (2 * D_) + D_ + d] = hv;
    }
}

// ------------------------- attention score + softmax -------------------------
// block = (t,b); alpha[t,b,p] = softmax_p( sum_a relu(att1[b,p,a]+att2[t,b,a])*Wfull[a] )
__global__ __launch_bounds__(256) void att_softmax_kernel(
    const float* __restrict__ att1, const float* __restrict__ att2,
    const float* __restrict__ Wfull, float* __restrict__ alpha)
{
    __shared__ float a2s[A_];
    __shared__ float wfl[A_];
    __shared__ float attv[P_];
    __shared__ float red[256];

    int tid = threadIdx.x;
    int t = blockIdx.x >> 6;
    int b = blockIdx.x & 63;

    const float* a2 = att2 + ((size_t)t * B_ + b) * A_;
#pragma unroll
    for (int i = 0; i < 2; i++) {
        int a = tid + i * 256;
        a2s[a] = a2[a];
        wfl[a] = Wfull[a];
    }
    __syncthreads();

    int warp = tid >> 5, lane = tid & 31;
    for (int p = warp; p < P_; p += 8) {
        const float* a1 = att1 + ((size_t)b * P_ + p) * A_;
        float s = 0.f;
        for (int a = lane; a < A_; a += 32) {
            float v = a1[a] + a2s[a];
            s += fmaxf(v, 0.f) * wfl[a];
        }
#pragma unroll
        for (int off = 16; off; off >>= 1) s += __shfl_xor_sync(0xffffffffu, s, off);
        if (lane == 0) attv[p] = s;
    }
    __syncthreads();

    float x = attv[tid];
    red[tid] = x;
    __syncthreads();
    for (int s = 128; s; s >>= 1) {
        if (tid < s) red[tid] = fmaxf(red[tid], red[tid + s]);
        __syncthreads();
    }
    float mx = red[0];
    __syncthreads();
    float e = expf(x - mx);
    red[tid] = e;
    __syncthreads();
    for (int s = 128; s; s >>= 1) {
        if (tid < s) red[tid] += red[tid + s];
        __syncthreads();
    }
    float sum = red[0];
    alpha[((size_t)t * B_ + b) * P_ + tid] = e / sum;
}

// awe[t,b,e] = sum_p alpha[t,b,p] * fh[b,p,e]   (block per b, 512 threads = e)
__global__ __launch_bounds__(512) void awe_kernel(
    const float* __restrict__ alpha, const float* __restrict__ fh,
    float* __restrict__ awe)
{
    __shared__ float al[T_][P_];
    int b = blockIdx.x;
    int tid = threadIdx.x;
#pragma unroll
    for (int i = 0; i < 8; i++) {
        int idx = tid + i * 512;
        int t = idx >> 8, p = idx & 255;
        al[t][p] = alpha[((size_t)t * B_ + b) * P_ + p];
    }
    __syncthreads();
    float acc[T_];
#pragma unroll
    for (int t = 0; t < T_; t++) acc[t] = 0.f;
    const float* fhb = fh + (size_t)b * P_ * E_;
    for (int p = 0; p < P_; p++) {
        float v = fhb[(size_t)p * E_ + tid];
#pragma unroll
        for (int t = 0; t < T_; t++) acc[t] += al[t][p] * v;
    }
#pragma unroll
    for (int t = 0; t < T_; t++)
        awe[((size_t)t * B_ + b) * E_ + tid] = acc[t];
}

// gate + gated concat -> fc_in. block per (t,b) row, 256 threads.
__global__ __launch_bounds__(256) void gate_kernel(
    const float* __restrict__ hidden, const float* __restrict__ awe,
    const float* __restrict__ Wg, const float* __restrict__ bg,
    float* __restrict__ fcin)
{
    __shared__ float s0[256];
    __shared__ float s1[256];
    const int F = 2 * D_ + E_;   // 1536
    int tid = threadIdx.x;
    size_t row = blockIdx.x;
    const float* hid = hidden + row * (2 * D_);
    const float* aw  = awe + row * E_;

    float p0 = 0.f, p1 = 0.f;
#pragma unroll
    for (int i = 0; i < 6; i++) {
        int k = tid + i * 256;
        float x = (k < 2 * D_) ? hid[k] : aw[k - 2 * D_];
        p0 += x * Wg[k];
        p1 += x * Wg[F + k];
    }
    s0[tid] = p0; s1[tid] = p1;
    __syncthreads();
    for (int s = 128; s; s >>= 1) {
        if (tid < s) { s0[tid] += s0[tid + s]; s1[tid] += s1[tid + s]; }
        __syncthreads();
    }
    float z0 = s0[0] + bg[0];
    float z1 = s1[0] + bg[1];
    float g0 = 1.f / (1.f + expf(z1 - z0));
    float g1 = 1.f - g0;
#pragma unroll
    for (int i = 0; i < 6; i++) {
        int k = tid + i * 256;
        float x = (k < 2 * D_) ? (g0 * hid[k]) : (g1 * aw[k - 2 * D_]);
        fcin[row * F + k] = x;
    }
}

// ------------------------------ launcher ------------------------------------
extern "C" void kernel_launch(void* const* d_in, const int* in_sizes, int n_in,
                              void* d_out, int out_size)
{
    const float* enc   = (const float*)d_in[0];
    const float* Wih1  = (const float*)d_in[1];
    const float* Whh1  = (const float*)d_in[2];
    const float* bih1  = (const float*)d_in[3];
    const float* bhh1  = (const float*)d_in[4];
    const float* Wih1r = (const float*)d_in[5];
    const float* Whh1r = (const float*)d_in[6];
    const float* bih1r = (const float*)d_in[7];
    const float* bhh1r = (const float*)d_in[8];
    const float* Wih2  = (const float*)d_in[9];
    const float* Whh2  = (const float*)d_in[10];
    const float* bih2  = (const float*)d_in[11];
    const float* bhh2  = (const float*)d_in[12];
    const float* Wih2r = (const float*)d_in[13];
    const float* Whh2r = (const float*)d_in[14];
    const float* bih2r = (const float*)d_in[15];
    const float* bhh2r = (const float*)d_in[16];
    const float* Wenc  = (const float*)d_in[17];
    const float* benc  = (const float*)d_in[18];
    const float* Wdec  = (const float*)d_in[19];
    const float* bdec  = (const float*)d_in[20];
    const float* Wfull = (const float*)d_in[21];
    // d_in[22] = bfull: softmax-shift-invariant, skipped.
    const float* Wg    = (const float*)d_in[23];
    const float* bg    = (const float*)d_in[24];
    const float* Wfc   = (const float*)d_in[25];
    const float* bfc   = (const float*)d_in[26];
    float* out = (float*)d_out;

    float *feats, *fh, *Xp1f, *Xp1r, *Xp2f, *Xp2r, *x2, *hidden, *state;
    float *att1, *att2, *alpha, *awe, *fcin;
    cudaGetSymbolAddress((void**)&feats,  g_feats);
    cudaGetSymbolAddress((void**)&fh,     g_fh);
    cudaGetSymbolAddress((void**)&Xp1f,   g_Xp1f);
    cudaGetSymbolAddress((void**)&Xp1r,   g_Xp1r);
    cudaGetSymbolAddress((void**)&Xp2f,   g_Xp2f);
    cudaGetSymbolAddress((void**)&Xp2r,   g_Xp2r);
    cudaGetSymbolAddress((void**)&x2,     g_x2);
    cudaGetSymbolAddress((void**)&hidden, g_hidden);
    cudaGetSymbolAddress((void**)&state,  g_state);
    cudaGetSymbolAddress((void**)&att1,   g_att1);
    cudaGetSymbolAddress((void**)&att2,   g_att2);
    cudaGetSymbolAddress((void**)&alpha,  g_alpha);
    cudaGetSymbolAddress((void**)&awe,    g_awe);
    cudaGetSymbolAddress((void**)&fcin,   g_fcin);

    float* hA = state;
    float* hB = state + 128 * D_;
    float* cb = state + 2 * 128 * D_;

    // 1. feats_hol transpose + pooled feats
    transpose_fh_kernel<<<dim3(16, 8, 64), dim3(32, 8)>>>(enc, fh);
    feats_kernel<<<(T_ * B_ * E_ + 255) / 256, 256>>>(enc, feats);

    // 2. layer-1 input projections (fold both biases)
    sgemm_nt<<<dim3(16, 8), 256>>>(feats, Wih1,  bih1,  bhh1,  Xp1f, T_ * B_, 4 * D_, E_);
    sgemm_nt<<<dim3(16, 8), 256>>>(feats, Wih1r, bih1r, bhh1r, Xp1r, T_ * B_, 4 * D_, E_);

    // 3. layer-1 recurrence (fwd+rev fused, h double-buffered)
    zero_kernel<<<(3 * 128 * D_ + 255) / 256, 256>>>(state, 3 * 128 * D_);
    for (int t = 0; t < T_; t++) {
        const float* hi = (t & 1) ? hB : hA;
        float*       ho = (t & 1) ? hA : hB;
        lstm_step_kernel<<<64, 256>>>(Xp1f, Xp1r, Whh1, Whh1r, hi, ho, cb, x2, t);
    }

    // 4. layer-2 input projections
    sgemm_nt<<<dim3(16, 8), 256>>>(x2, Wih2,  bih2,  bhh2,  Xp2f, T_ * B_, 4 * D_, 2 * D_);
    sgemm_nt<<<dim3(16, 8), 256>>>(x2, Wih2r, bih2r, bhh2r, Xp2r, T_ * B_, 4 * D_, 2 * D_);

    // 5. layer-2 recurrence
    zero_kernel<<<(3 * 128 * D_ + 255) / 256, 256>>>(state, 3 * 128 * D_);
    for (int t = 0; t < T_; t++) {
        const float* hi = (t & 1) ? hB : hA;
        float*       ho = (t & 1) ? hA : hB;
        lstm_step_kernel<<<64, 256>>>(Xp2f, Xp2r, Whh2, Whh2r, hi, ho, cb, hidden, t);
    }

    // 6. attention
    sgemm_nt<<<dim3(4, 128), 256>>>(fh,     Wenc, benc, nullptr, att1, B_ * P_, A_, E_);
    sgemm_nt<<<dim3(4, 8),   256>>>(hidden, Wdec, bdec, nullptr, att2, T_ * B_, A_, 2 * D_);
    att_softmax_kernel<<<T_ * B_, 256>>>(att1, att2, Wfull, alpha);
    awe_kernel<<<B_, 512>>>(alpha, fh, awe);

    // 7. gate + gated concat
    gate_kernel<<<T_ * B_, 256>>>(hidden, awe, Wg, bg, fcin);

    // 8. final classifier
    sgemm_nt<<<dim3((V_ + 127) / 128, 8), 256>>>(fcin, Wfc, bfc, nullptr, out,
                                                 T_ * B_, V_, 2 * D_ + E_);
}

// round 2
// speedup vs baseline: 1.3409x; 1.3409x over previous
#include <cuda_runtime.h>
#include <cuda_bf16.h>
#include <math.h>
#include <stdint.h>

// ---------------------------------------------------------------------------
// DecoderWithAttention: B=64, E=512, H=W=16, T=16, D=512, A=512, V=5000
// All GEMMs (incl. LSTM gate GEMM) on tensor cores: tf32 mma with hi/lo
// compensation (3 mma per tile) => fp32-grade accuracy at tensor-core speed.
// ---------------------------------------------------------------------------

#define B_ 64
#define E_ 512
#define T_ 16
#define D_ 512
#define P_ 256
#define A_ 512
#define V_ 5000

// ------------------------------ scratch ------------------------------------
__device__ float g_feats [T_ * B_ * E_];
__device__ float g_fh    [B_ * P_ * E_];
__device__ float g_Xp1f  [T_ * B_ * 4 * D_];
__device__ float g_Xp1r  [T_ * B_ * 4 * D_];
__device__ float g_Xp2f  [T_ * B_ * 4 * D_];
__device__ float g_Xp2r  [T_ * B_ * 4 * D_];
__device__ float g_x2    [T_ * B_ * 2 * D_];
__device__ float g_hidden[T_ * B_ * 2 * D_];
__device__ float g_state [3 * 128 * D_];          // hA | hB | c
__device__ float g_att1  [B_ * P_ * A_];
__device__ float g_att2  [T_ * B_ * A_];
__device__ float g_alpha [T_ * B_ * P_];
__device__ float g_awe   [T_ * B_ * E_];
__device__ float g_fcin  [T_ * B_ * (E_ + 2 * D_)];

// ------------------------------ helpers ------------------------------------
__device__ __forceinline__ float tf32_rna(float x) {
    uint32_t u;
    asm("cvt.rna.tf32.f32 %0, %1;" : "=r"(u) : "f"(x));
    return __uint_as_float(u);
}

__device__ __forceinline__ void mma_tf32(float* d, const uint32_t* a, const uint32_t* b) {
    asm volatile(
        "mma.sync.aligned.m16n8k8.row.col.f32.tf32.tf32.f32 "
        "{%0,%1,%2,%3}, {%4,%5,%6,%7}, {%8,%9}, {%0,%1,%2,%3};\n"
        : "+f"(d[0]), "+f"(d[1]), "+f"(d[2]), "+f"(d[3])
        : "r"(a[0]), "r"(a[1]), "r"(a[2]), "r"(a[3]), "r"(b[0]), "r"(b[1]));
}

__global__ void zero_kernel(float* __restrict__ p, int n) {
    int i = blockIdx.x * blockDim.x + threadIdx.x;
    if (i < n) p[i] = 0.f;
}

// fh[b][p][e] = enc[b][e][p]
__global__ void transpose_fh_kernel(const float* __restrict__ enc, float* __restrict__ fh) {
    __shared__ float tile[32][33];
    int b  = blockIdx.z;
    int e0 = blockIdx.x * 32;
    int p0 = blockIdx.y * 32;
    int x = threadIdx.x;
#pragma unroll
    for (int i = 0; i < 4; i++) {
        int y = threadIdx.y + i * 8;
        tile[y][x] = enc[((size_t)b * E_ + e0 + y) * P_ + p0 + x];
    }
    __syncthreads();
#pragma unroll
    for (int i = 0; i < 4; i++) {
        int y = threadIdx.y + i * 8;
        fh[((size_t)b * P_ + p0 + y) * E_ + e0 + x] = tile[x][y];
    }
}

// feats[t][b][e] = mean_h enc[b][e][h*16 + t]
__global__ void feats_kernel(const float* __restrict__ enc, float* __restrict__ feats) {
    int gi = blockIdx.x * blockDim.x + threadIdx.x;
    if (gi >= T_ * B_ * E_) return;
    int t = gi & 15;
    int e = (gi >> 4) & (E_ - 1);
    int b = gi >> 13;
    const float* src = enc + ((size_t)b * E_ + e) * P_ + t;
    float s = 0.f;
#pragma unroll
    for (int h = 0; h < 16; h++) s += src[h * 16];
    feats[((size_t)t * B_ + b) * E_ + e] = s * (1.f / 16.f);
}

// ---------------------- tf32 hi/lo GEMM (NT) --------------------------------
// C[m][n] = sum_k A[m][k]*W[n][k] + b1[n] + b2[n]
// BM=128, BN=64, BK=16, 256 threads (8 warps = 4x2), warp tile 32x32.
// M % 128 == 0, K % 16 == 0, N arbitrary (guarded).
#define GST 20   // smem row stride (16 + 4 pad)

__global__ __launch_bounds__(256) void gemm_tf32(
    const float* __restrict__ A, const float* __restrict__ W,
    const float* __restrict__ b1, const float* __restrict__ b2,
    float* __restrict__ C, int M, int N, int K)
{
    __shared__ float Ah[128][GST], Al[128][GST];
    __shared__ float Bh[64][GST],  Bl[64][GST];

    int tid  = threadIdx.x;
    int wid  = tid >> 5, lane = tid & 31;
    int g = lane >> 2, tq = lane & 3;
    int m0b = blockIdx.y * 128, n0b = blockIdx.x * 64;
    int wm = (wid >> 1) * 32, wn = (wid & 1) * 32;

    float acc[2][4][4];
#pragma unroll
    for (int i = 0; i < 2; i++)
#pragma unroll
        for (int j = 0; j < 4; j++)
#pragma unroll
            for (int v = 0; v < 4; v++) acc[i][j][v] = 0.f;

    int arow = tid >> 1, af4 = (tid & 1) * 2;   // 2 float4 per thread
    int brow = tid >> 2, bf4 = tid & 3;         // 1 float4 per thread

    for (int k0 = 0; k0 < K; k0 += 16) {
        // ---- A tile 128x16 ----
#pragma unroll
        for (int i = 0; i < 2; i++) {
            float4 v = *(const float4*)(A + (size_t)(m0b + arow) * K + k0 + (af4 + i) * 4);
            int c = (af4 + i) * 4;
            float hx = tf32_rna(v.x), hy = tf32_rna(v.y), hz = tf32_rna(v.z), hw = tf32_rna(v.w);
            Ah[arow][c+0] = hx; Ah[arow][c+1] = hy; Ah[arow][c+2] = hz; Ah[arow][c+3] = hw;
            Al[arow][c+0] = tf32_rna(v.x - hx); Al[arow][c+1] = tf32_rna(v.y - hy);
            Al[arow][c+2] = tf32_rna(v.z - hz); Al[arow][c+3] = tf32_rna(v.w - hw);
        }
        // ---- B tile 64x16 (rows = output cols, guarded) ----
        {
            int gn = n0b + brow;
            float4 v = make_float4(0.f, 0.f, 0.f, 0.f);
            if (gn < N) v = *(const float4*)(W + (size_t)gn * K + k0 + bf4 * 4);
            int c = bf4 * 4;
            float hx = tf32_rna(v.x), hy = tf32_rna(v.y), hz = tf32_rna(v.z), hw = tf32_rna(v.w);
            Bh[brow][c+0] = hx; Bh[brow][c+1] = hy; Bh[brow][c+2] = hz; Bh[brow][c+3] = hw;
            Bl[brow][c+0] = tf32_rna(v.x - hx); Bl[brow][c+1] = tf32_rna(v.y - hy);
            Bl[brow][c+2] = tf32_rna(v.z - hz); Bl[brow][c+3] = tf32_rna(v.w - hw);
        }
        __syncthreads();

#pragma unroll
        for (int ks = 0; ks < 16; ks += 8) {
            uint32_t ah[2][4], al[2][4], bh[4][2], bl[4][2];
#pragma unroll
            for (int i = 0; i < 2; i++) {
                int r = wm + i * 16;
                ah[i][0] = __float_as_uint(Ah[r+g  ][ks+tq  ]);
                ah[i][1] = __float_as_uint(Ah[r+g+8][ks+tq  ]);
                ah[i][2] = __float_as_uint(Ah[r+g  ][ks+tq+4]);
                ah[i][3] = __float_as_uint(Ah[r+g+8][ks+tq+4]);
                al[i][0] = __float_as_uint(Al[r+g  ][ks+tq  ]);
                al[i][1] = __float_as_uint(Al[r+g+8][ks+tq  ]);
                al[i][2] = __float_as_uint(Al[r+g  ][ks+tq+4]);
                al[i][3] = __float_as_uint(Al[r+g+8][ks+tq+4]);
            }
#pragma unroll
            for (int j = 0; j < 4; j++) {
                int n = wn + j * 8 + g;
                bh[j][0] = __float_as_uint(Bh[n][ks+tq  ]);
                bh[j][1] = __float_as_uint(Bh[n][ks+tq+4]);
                bl[j][0] = __float_as_uint(Bl[n][ks+tq  ]);
                bl[j][1] = __float_as_uint(Bl[n][ks+tq+4]);
            }
#pragma unroll
            for (int i = 0; i < 2; i++)
#pragma unroll
                for (int j = 0; j < 4; j++) {
                    mma_tf32(acc[i][j], ah[i], bh[j]);
                    mma_tf32(acc[i][j], ah[i], bl[j]);
                    mma_tf32(acc[i][j], al[i], bh[j]);
                }
        }
        __syncthreads();
    }

#pragma unroll
    for (int i = 0; i < 2; i++)
#pragma unroll
        for (int j = 0; j < 4; j++) {
            int r  = m0b + wm + i * 16 + g;
            int c0 = n0b + wn + j * 8 + 2 * tq;
#pragma unroll
            for (int cc = 0; cc < 2; cc++) {
                int c = c0 + cc;
                if (c < N) {
                    float bias = (b1 ? b1[c] : 0.f) + (b2 ? b2[c] : 0.f);
                    C[(size_t)r * N + c]       = acc[i][j][cc]     + bias;
                    C[(size_t)(r+8) * N + c]   = acc[i][j][2+cc]   + bias;
                }
            }
        }
}

// ---------------------- fused LSTM step (tf32 mma) ---------------------------
// Rows 0..63 fwd (Whf, Xpf[t]); rows 64..127 rev (Whr, Xpr[15-t]).
// Block owns d-slice [d0,d0+8) => 32 gate cols (tile j == gate j).
// Warp w covers rows w*16..w*16+15; warps 0-3 use Whf, 4-7 use Whr.
__global__ __launch_bounds__(256) void lstm_step_mma(
    const float* __restrict__ Xpf, const float* __restrict__ Xpr,
    const float* __restrict__ Whf, const float* __restrict__ Whr,
    const float* __restrict__ hIn, float* __restrict__ hOut,
    float* __restrict__ cbuf, float* __restrict__ outbuf, int t)
{
    __shared__ float Hh[128][GST], Hl[128][GST];
    __shared__ float Wfh[32][GST], Wfl[32][GST];
    __shared__ float Wrh[32][GST], Wrl[32][GST];

    int tid  = threadIdx.x;
    int wid  = tid >> 5, lane = tid & 31;
    int g = lane >> 2, tq = lane & 3;
    int d0 = blockIdx.x * 8;
    int wm = wid * 16;

    float acc[4][4];
#pragma unroll
    for (int j = 0; j < 4; j++)
#pragma unroll
        for (int v = 0; v < 4; v++) acc[j][v] = 0.f;

    int arow = tid >> 1, af4 = (tid & 1) * 2;
    int widx = tid & 127;
    int nw = widx >> 2, wf4 = widx & 3;
    int wrow = (nw >> 3) * D_ + d0 + (nw & 7);
    const float* Wsrc = (tid < 128) ? Whf : Whr;
    float (*WsH)[GST] = (tid < 128) ? Wfh : Wrh;
    float (*WsL)[GST] = (tid < 128) ? Wfl : Wrl;

    for (int k0 = 0; k0 < D_; k0 += 16) {
        // H tile 128x16
#pragma unroll
        for (int i = 0; i < 2; i++) {
            float4 v = *(const float4*)(hIn + (size_t)arow * D_ + k0 + (af4 + i) * 4);
            int c = (af4 + i) * 4;
            float hx = tf32_rna(v.x), hy = tf32_rna(v.y), hz = tf32_rna(v.z), hw = tf32_rna(v.w);
            Hh[arow][c+0] = hx; Hh[arow][c+1] = hy; Hh[arow][c+2] = hz; Hh[arow][c+3] = hw;
            Hl[arow][c+0] = tf32_rna(v.x - hx); Hl[arow][c+1] = tf32_rna(v.y - hy);
            Hl[arow][c+2] = tf32_rna(v.z - hz); Hl[arow][c+3] = tf32_rna(v.w - hw);
        }
        // W tiles: 2 x (32x16); threads 0-127 fwd, 128-255 rev
        {
            float4 v = *(const float4*)(Wsrc + (size_t)wrow * D_ + k0 + wf4 * 4);
            int c = wf4 * 4;
            float hx = tf32_rna(v.x), hy = tf32_rna(v.y), hz = tf32_rna(v.z), hw = tf32_rna(v.w);
            WsH[nw][c+0] = hx; WsH[nw][c+1] = hy; WsH[nw][c+2] = hz; WsH[nw][c+3] = hw;
            WsL[nw][c+0] = tf32_rna(v.x - hx); WsL[nw][c+1] = tf32_rna(v.y - hy);
            WsL[nw][c+2] = tf32_rna(v.z - hz); WsL[nw][c+3] = tf32_rna(v.w - hw);
        }
        __syncthreads();

        float (*RH)[GST] = (wid < 4) ? Wfh : Wrh;
        float (*RL)[GST] = (wid < 4) ? Wfl : Wrl;
#pragma unroll
        for (int ks = 0; ks < 16; ks += 8) {
            uint32_t ah[4], al[4], bh[4][2], bl[4][2];
            ah[0] = __float_as_uint(Hh[wm+g  ][ks+tq  ]);
            ah[1] = __float_as_uint(Hh[wm+g+8][ks+tq  ]);
            ah[2] = __float_as_uint(Hh[wm+g  ][ks+tq+4]);
            ah[3] = __float_as_uint(Hh[wm+g+8][ks+tq+4]);
            al[0] = __float_as_uint(Hl[wm+g  ][ks+tq  ]);
            al[1] = __float_as_uint(Hl[wm+g+8][ks+tq  ]);
            al[2] = __float_as_uint(Hl[wm+g  ][ks+tq+4]);
            al[3] = __float_as_uint(Hl[wm+g+8][ks+tq+4]);
#pragma unroll
            for (int j = 0; j < 4; j++) {
                int n = j * 8 + g;
                bh[j][0] = __float_as_uint(RH[n][ks+tq  ]);
                bh[j][1] = __float_as_uint(RH[n][ks+tq+4]);
                bl[j][0] = __float_as_uint(RL[n][ks+tq  ]);
                bl[j][1] = __float_as_uint(RL[n][ks+tq+4]);
            }
#pragma unroll
            for (int j = 0; j < 4; j++) {
                mma_tf32(acc[j], ah, bh[j]);
                mma_tf32(acc[j], ah, bl[j]);
                mma_tf32(acc[j], al, bh[j]);
            }
        }
        __syncthreads();
    }

    // epilogue: thread holds all 4 gates for rows {wm+g, wm+g+8}, d = d0+2tq(+1)
#pragma unroll
    for (int rr = 0; rr < 2; rr++) {
        int r = wm + g + rr * 8;
        bool fwd = (r < 64);
        const float* xp = fwd
            ? (Xpf + ((size_t)t * B_ + r) * (4 * D_))
            : (Xpr + ((size_t)(15 - t) * B_ + (r - 64)) * (4 * D_));
#pragma unroll
        for (int cc = 0; cc < 2; cc++) {
            int d  = d0 + 2 * tq + cc;
            int vi = rr * 2 + cc;
            float iv = acc[0][vi] + xp[0 * D_ + d];
            float fv = acc[1][vi] + xp[1 * D_ + d];
            float gv = acc[2][vi] + xp[2 * D_ + d];
            float ov = acc[3][vi] + xp[3 * D_ + d];
            float co = cbuf[(size_t)r * D_ + d];
            float si = 1.f / (1.f + expf(-iv));
            float sf = 1.f / (1.f + expf(-fv));
            float so = 1.f / (1.f + expf(-ov));
            float cn = sf * co + si * tanhf(gv);
            float hv = so * tanhf(cn);
            cbuf[(size_t)r * D_ + d] = cn;
            hOut[(size_t)r * D_ + d] = hv;
            if (fwd)
                outbuf[((size_t)t * B_ + r) * (2 * D_) + d] = hv;
            else
                outbuf[((size_t)(15 - t) * B_ + (r - 64)) * (2 * D_) + D_ + d] = hv;
        }
    }
}

// ------------------------- attention score + softmax -------------------------
__global__ __launch_bounds__(256) void att_softmax_kernel(
    const float* __restrict__ att1, const float* __restrict__ att2,
    const float* __restrict__ Wfull, float* __restrict__ alpha)
{
    __shared__ float a2s[A_];
    __shared__ float wfl[A_];
    __shared__ float attv[P_];
    __shared__ float red[256];

    int tid = threadIdx.x;
    int t = blockIdx.x >> 6;
    int b = blockIdx.x & 63;

    const float* a2 = att2 + ((size_t)t * B_ + b) * A_;
#pragma unroll
    for (int i = 0; i < 2; i++) {
        int a = tid + i * 256;
        a2s[a] = a2[a];
        wfl[a] = Wfull[a];
    }
    __syncthreads();

    int warp = tid >> 5, lane = tid & 31;
    for (int p = warp; p < P_; p += 8) {
        const float* a1 = att1 + ((size_t)b * P_ + p) * A_;
        float s = 0.f;
        for (int a = lane; a < A_; a += 32) {
            float v = a1[a] + a2s[a];
            s += fmaxf(v, 0.f) * wfl[a];
        }
#pragma unroll
        for (int off = 16; off; off >>= 1) s += __shfl_xor_sync(0xffffffffu, s, off);
        if (lane == 0) attv[p] = s;
    }
    __syncthreads();

    float x = attv[tid];
    red[tid] = x;
    __syncthreads();
    for (int s = 128; s; s >>= 1) {
        if (tid < s) red[tid] = fmaxf(red[tid], red[tid + s]);
        __syncthreads();
    }
    float mx = red[0];
    __syncthreads();
    float e = expf(x - mx);
    red[tid] = e;
    __syncthreads();
    for (int s = 128; s; s >>= 1) {
        if (tid < s) red[tid] += red[tid + s];
        __syncthreads();
    }
    float sum = red[0];
    alpha[((size_t)t * B_ + b) * P_ + tid] = e / sum;
}

// awe[t,b,e] = sum_p alpha[t,b,p] * fh[b,p,e]
__global__ __launch_bounds__(512) void awe_kernel(
    const float* __restrict__ alpha, const float* __restrict__ fh,
    float* __restrict__ awe)
{
    __shared__ float al[T_][P_];
    int b = blockIdx.x;
    int tid = threadIdx.x;
#pragma unroll
    for (int i = 0; i < 8; i++) {
        int idx = tid + i * 512;
        int t = idx >> 8, p = idx & 255;
        al[t][p] = alpha[((size_t)t * B_ + b) * P_ + p];
    }
    __syncthreads();
    float acc[T_];
#pragma unroll
    for (int t = 0; t < T_; t++) acc[t] = 0.f;
    const float* fhb = fh + (size_t)b * P_ * E_;
    for (int p = 0; p < P_; p++) {
        float v = fhb[(size_t)p * E_ + tid];
#pragma unroll
        for (int t = 0; t < T_; t++) acc[t] += al[t][p] * v;
    }
#pragma unroll
    for (int t = 0; t < T_; t++)
        awe[((size_t)t * B_ + b) * E_ + tid] = acc[t];
}

// gate + gated concat -> fc_in
__global__ __launch_bounds__(256) void gate_kernel(
    const float* __restrict__ hidden, const float* __restrict__ awe,
    const float* __restrict__ Wg, const float* __restrict__ bg,
    float* __restrict__ fcin)
{
    __shared__ float s0[256];
    __shared__ float s1[256];
    const int F = 2 * D_ + E_;   // 1536
    int tid = threadIdx.x;
    size_t row = blockIdx.x;
    const float* hid = hidden + row * (2 * D_);
    const float* aw  = awe + row * E_;

    float p0 = 0.f, p1 = 0.f;
#pragma unroll
    for (int i = 0; i < 6; i++) {
        int k = tid + i * 256;
        float x = (k < 2 * D_) ? hid[k] : aw[k - 2 * D_];
        p0 += x * Wg[k];
        p1 += x * Wg[F + k];
    }
    s0[tid] = p0; s1[tid] = p1;
    __syncthreads();
    for (int s = 128; s; s >>= 1) {
        if (tid < s) { s0[tid] += s0[tid + s]; s1[tid] += s1[tid + s]; }
        __syncthreads();
    }
    float z0 = s0[0] + bg[0];
    float z1 = s1[0] + bg[1];
    float g0 = 1.f / (1.f + expf(z1 - z0));
    float g1 = 1.f - g0;
#pragma unroll
    for (int i = 0; i < 6; i++) {
        int k = tid + i * 256;
        float x = (k < 2 * D_) ? (g0 * hid[k]) : (g1 * aw[k - 2 * D_]);
        fcin[row * F + k] = x;
    }
}

// ------------------------------ launcher ------------------------------------
extern "C" void kernel_launch(void* const* d_in, const int* in_sizes, int n_in,
                              void* d_out, int out_size)
{
    const float* enc   = (const float*)d_in[0];
    const float* Wih1  = (const float*)d_in[1];
    const float* Whh1  = (const float*)d_in[2];
    const float* bih1  = (const float*)d_in[3];
    const float* bhh1  = (const float*)d_in[4];
    const float* Wih1r = (const float*)d_in[5];
    const float* Whh1r = (const float*)d_in[6];
    const float* bih1r = (const float*)d_in[7];
    const float* bhh1r = (const float*)d_in[8];
    const float* Wih2  = (const float*)d_in[9];
    const float* Whh2  = (const float*)d_in[10];
    const float* bih2  = (const float*)d_in[11];
    const float* bhh2  = (const float*)d_in[12];
    const float* Wih2r = (const float*)d_in[13];
    const float* Whh2r = (const float*)d_in[14];
    const float* bih2r = (const float*)d_in[15];
    const float* bhh2r = (const float*)d_in[16];
    const float* Wenc  = (const float*)d_in[17];
    const float* benc  = (const float*)d_in[18];
    const float* Wdec  = (const float*)d_in[19];
    const float* bdec  = (const float*)d_in[20];
    const float* Wfull = (const float*)d_in[21];
    // d_in[22] = bfull: softmax-shift-invariant, skipped.
    const float* Wg    = (const float*)d_in[23];
    const float* bg    = (const float*)d_in[24];
    const float* Wfc   = (const float*)d_in[25];
    const float* bfc   = (const float*)d_in[26];
    float* out = (float*)d_out;

    float *feats, *fh, *Xp1f, *Xp1r, *Xp2f, *Xp2r, *x2, *hidden, *state;
    float *att1, *att2, *alpha, *awe, *fcin;
    cudaGetSymbolAddress((void**)&feats,  g_feats);
    cudaGetSymbolAddress((void**)&fh,     g_fh);
    cudaGetSymbolAddress((void**)&Xp1f,   g_Xp1f);
    cudaGetSymbolAddress((void**)&Xp1r,   g_Xp1r);
    cudaGetSymbolAddress((void**)&Xp2f,   g_Xp2f);
    cudaGetSymbolAddress((void**)&Xp2r,   g_Xp2r);
    cudaGetSymbolAddress((void**)&x2,     g_x2);
    cudaGetSymbolAddress((void**)&hidden, g_hidden);
    cudaGetSymbolAddress((void**)&state,  g_state);
    cudaGetSymbolAddress((void**)&att1,   g_att1);
    cudaGetSymbolAddress((void**)&att2,   g_att2);
    cudaGetSymbolAddress((void**)&alpha,  g_alpha);
    cudaGetSymbolAddress((void**)&awe,    g_awe);
    cudaGetSymbolAddress((void**)&fcin,   g_fcin);

    float* hA = state;
    float* hB = state + 128 * D_;
    float* cb = state + 2 * 128 * D_;

    // 1. feats_hol transpose + pooled feats
    transpose_fh_kernel<<<dim3(16, 8, 64), dim3(32, 8)>>>(enc, fh);
    feats_kernel<<<(T_ * B_ * E_ + 255) / 256, 256>>>(enc, feats);

    // 2. layer-1 input projections
    gemm_tf32<<<dim3(32, 8), 256>>>(feats, Wih1,  bih1,  bhh1,  Xp1f, T_ * B_, 4 * D_, E_);
    gemm_tf32<<<dim3(32, 8), 256>>>(feats, Wih1r, bih1r, bhh1r, Xp1r, T_ * B_, 4 * D_, E_);

    // 3. layer-1 recurrence
    zero_kernel<<<(3 * 128 * D_ + 255) / 256, 256>>>(state, 3 * 128 * D_);
    for (int t = 0; t < T_; t++) {
        const float* hi = (t & 1) ? hB : hA;
        float*       ho = (t & 1) ? hA : hB;
        lstm_step_mma<<<64, 256>>>(Xp1f, Xp1r, Whh1, Whh1r, hi, ho, cb, x2, t);
    }

    // 4. layer-2 input projections
    gemm_tf32<<<dim3(32, 8), 256>>>(x2, Wih2,  bih2,  bhh2,  Xp2f, T_ * B_, 4 * D_, 2 * D_);
    gemm_tf32<<<dim3(32, 8), 256>>>(x2, Wih2r, bih2r, bhh2r, Xp2r, T_ * B_, 4 * D_, 2 * D_);

    // 5. layer-2 recurrence
    zero_kernel<<<(3 * 128 * D_ + 255) / 256, 256>>>(state, 3 * 128 * D_);
    for (int t = 0; t < T_; t++) {
        const float* hi = (t & 1) ? hB : hA;
        float*       ho = (t & 1) ? hA : hB;
        lstm_step_mma<<<64, 256>>>(Xp2f, Xp2r, Whh2, Whh2r, hi, ho, cb, hidden, t);
    }

    // 6. attention
    gemm_tf32<<<dim3(8, 128), 256>>>(fh,     Wenc, benc, nullptr, att1, B_ * P_, A_, E_);
    gemm_tf32<<<dim3(8, 8),   256>>>(hidden, Wdec, bdec, nullptr, att2, T_ * B_, A_, 2 * D_);
    att_softmax_kernel<<<T_ * B_, 256>>>(att1, att2, Wfull, alpha);
    awe_kernel<<<B_, 512>>>(alpha, fh, awe);

    // 7. gate + gated concat
    gate_kernel<<<T_ * B_, 256>>>(hidden, awe, Wg, bg, fcin);

    // 8. final classifier
    gemm_tf32<<<dim3((V_ + 63) / 64, 8), 256>>>(fcin, Wfc, bfc, nullptr, out,
                                                T_ * B_, V_, 2 * D_ + E_);
}